// round 14
// baseline (speedup 1.0000x reference)
#include <cuda_runtime.h>
#include <math.h>

#define C_TOT 256
#define C_HID 128
#define HH 512
#define WW 512
#define HW (HH * WW)          // 262144
#define HW4 (HW / 4)          // 65536
#define N_TILES (HW4 / 16)   // 4096 tiles of 16 float4 pixel-columns
#define N_BLOCKS 296          // 148 SMs x occ 2, single persistent wave
#define EPSLN 1e-5f

// Scratch (device globals; no allocation allowed)
__device__ float g_part[C_TOT * 4];       // partial channel sums
__device__ float g_params[2 * C_TOT + 1]; // [0..255]=ch_attn, [256..511]=w_eff, [512]=b_eff

// ---------------------------------------------------------------------------
// Kernel 1: per-channel partial sums of x. Already at 80.3% DRAM / 6.35 TB/s.
// ---------------------------------------------------------------------------
__global__ __launch_bounds__(256) void k_sum(const float* __restrict__ x) {
    const int c = blockIdx.x;
    const int chunk = blockIdx.y;
    const int t = threadIdx.x;
    const float4* xp = reinterpret_cast<const float4*>(x)
                     + (size_t)c * HW4 + (size_t)chunk * (HW4 / 4);

    float s = 0.0f;
#pragma unroll 8
    for (int i = t; i < HW4 / 4; i += 256) {
        float4 v = xp[i];
        s += (v.x + v.y) + (v.z + v.w);
    }
    __shared__ float sm[256];
    sm[t] = s;
    __syncthreads();
#pragma unroll
    for (int off = 128; off > 0; off >>= 1) {
        if (t < off) sm[t] += sm[t + off];
        __syncthreads();
    }
    if (t == 0) g_part[c * 4 + chunk] = sm[0];
}

// ---------------------------------------------------------------------------
// Kernel 2: all the tiny math. One block, 256 threads.
// ---------------------------------------------------------------------------
__device__ __forceinline__ float block_reduce_sum(float v, float* red, int t) {
    red[t] = v;
    __syncthreads();
#pragma unroll
    for (int off = 128; off > 0; off >>= 1) {
        if (t < off) red[t] += red[t + off];
        __syncthreads();
    }
    float r = red[0];
    __syncthreads();
    return r;
}

__device__ __forceinline__ float block_reduce_max(float v, float* red, int t) {
    red[t] = v;
    __syncthreads();
#pragma unroll
    for (int off = 128; off > 0; off >>= 1) {
        if (t < off) red[t] = fmaxf(red[t], red[t + off]);
        __syncthreads();
    }
    float r = red[0];
    __syncthreads();
    return r;
}

__global__ __launch_bounds__(256) void k_small(
    const float* __restrict__ ch_cv1_w, const float* __restrict__ ch_cv1_b,
    const float* __restrict__ ch_cv3_w, const float* __restrict__ ch_cv3_b,
    const float* __restrict__ ln_g,     const float* __restrict__ ln_b,
    const float* __restrict__ sp_cv1_w, const float* __restrict__ sp_cv1_b,
    const float* __restrict__ sp_cv2_w, const float* __restrict__ sp_cv2_b)
{
    __shared__ float xsum[C_TOT];
    __shared__ float yv[C_HID];
    __shared__ float s2[C_HID];
    __shared__ float red[C_TOT];

    const int t = threadIdx.x;

    xsum[t] = g_part[t * 4] + g_part[t * 4 + 1] + g_part[t * 4 + 2] + g_part[t * 4 + 3];
    __syncthreads();

    // y = ch_cv1_w @ xsum + HW * ch_cv1_b   (128)
    if (t < C_HID) {
        float a = 0.0f;
#pragma unroll 4
        for (int c = 0; c < C_TOT; c++) a = fmaf(ch_cv1_w[t * C_TOT + c], xsum[c], a);
        yv[t] = a + (float)HW * ch_cv1_b[t];
    }
    __syncthreads();

    // z = ch_cv3_w @ y + ch_cv3_b   (256)
    float z = ch_cv3_b[t];
#pragma unroll 4
    for (int j = 0; j < C_HID; j++) z = fmaf(ch_cv3_w[t * C_HID + j], yv[j], z);

    // LayerNorm over 256 (population variance), then sigmoid -> ch_attn
    float mu = block_reduce_sum(z, red, t) * (1.0f / C_TOT);
    float d = z - mu;
    float var = block_reduce_sum(d * d, red, t) * (1.0f / C_TOT);
    float zn = d * rsqrtf(var + EPSLN);
    float aff = zn * ln_g[t] + ln_b[t];
    g_params[t] = 1.0f / (1.0f + expf(-aff));

    // s2pre = sp_cv2_w @ (xsum/HW) + sp_cv2_b ; softmax over 128
    float s2pre = -INFINITY;
    if (t < C_HID) {
        float a = 0.0f;
#pragma unroll 4
        for (int c = 0; c < C_TOT; c++) a = fmaf(sp_cv2_w[t * C_TOT + c], xsum[c], a);
        s2pre = a * (1.0f / (float)HW) + sp_cv2_b[t];
    }
    float m = block_reduce_max(s2pre, red, t);
    float e = (t < C_HID) ? expf(s2pre - m) : 0.0f;
    float esum = block_reduce_sum(e, red, t);
    if (t < C_HID) s2[t] = e / esum;
    __syncthreads();

    // w_eff[c] = sum_j s2[j] * sp_cv1_w[j, c]
    float we = 0.0f;
#pragma unroll 4
    for (int j = 0; j < C_HID; j++) we = fmaf(s2[j], sp_cv1_w[j * C_TOT + t], we);
    g_params[C_TOT + t] = we;

    // b_eff = dot(s2, sp_cv1_b)
    float bcontrib = (t < C_HID) ? s2[t] * sp_cv1_b[t] : 0.0f;
    float be = block_reduce_sum(bcontrib, red, t);
    if (t == 0) g_params[2 * C_TOT] = be;
}

// ---------------------------------------------------------------------------
// Kernel 3: PERSISTENT fused spatial dot + output. 296 blocks (148 SM x occ 2),
// block (16,32) = 512 thr, grid-stride loop over 4096 tiles (~14 per block).
// Within the loop, each tile's STGs drain concurrently with the next tile's
// LDGs (stores are fire-and-forget) -> load/store overlap no longer depends
// on a co-resident block; occ=2 adds a second independent overlap source.
// Tile = 64 pixels (16 float4 cols) x 256 channels; each thread caches
// 8 channels x 1 float4 in registers (x read exactly once). Reduction:
// planar smem padded to stride 17 (coprime 32 -> conflict-free transposed
// read), warp w reduces pixel column w via shuffle butterfly. 2 barriers/tile.
// ---------------------------------------------------------------------------
__global__ __launch_bounds__(512, 2) void k_main(const float* __restrict__ x,
                                                 float* __restrict__ out)
{
    __shared__ float s_we[C_TOT];
    __shared__ float s_attn[C_TOT];
    __shared__ float s_ax[32][17];   // [channel grp][pixel col], padded
    __shared__ float s_ay[32][17];
    __shared__ float s_az[32][17];
    __shared__ float s_aw[32][17];
    __shared__ float4 s_sig[16];

    const int tx = threadIdx.x;      // pixel column 0..15
    const int ty = threadIdx.y;      // channel group 0..31
    const int t = ty * 16 + tx;      // linear 0..511
    const int w = t >> 5;            // warp id 0..15
    const int lane = t & 31;

    if (t < C_TOT) {
        s_attn[t] = g_params[t];
        s_we[t]   = g_params[C_TOT + t];
    }
    const float be = g_params[2 * C_TOT];
    __syncthreads();

    const float4* x4 = reinterpret_cast<const float4*>(x);
    float4* o4 = reinterpret_cast<float4*>(out);
    const int c0 = ty * 8;
    const float at0 = s_attn[c0 + 0], at1 = s_attn[c0 + 1];
    const float at2 = s_attn[c0 + 2], at3 = s_attn[c0 + 3];
    const float at4 = s_attn[c0 + 4], at5 = s_attn[c0 + 5];
    const float at6 = s_attn[c0 + 6], at7 = s_attn[c0 + 7];
    const float atv[8] = {at0, at1, at2, at3, at4, at5, at6, at7};
    float wev[8];
#pragma unroll
    for (int i = 0; i < 8; i++) wev[i] = s_we[c0 + i];

    for (int tile = blockIdx.x; tile < N_TILES; tile += N_BLOCKS) {
        const int pos4 = tile * 16 + tx;   // float4 index within HW

        float4 xv[8];
        float4 acc = make_float4(0.f, 0.f, 0.f, 0.f);
#pragma unroll
        for (int i = 0; i < 8; i++) {
            float4 v = x4[(size_t)(c0 + i) * HW4 + pos4];
            xv[i] = v;
            const float wgt = wev[i];
            acc.x = fmaf(wgt, v.x, acc.x);
            acc.y = fmaf(wgt, v.y, acc.y);
            acc.z = fmaf(wgt, v.z, acc.z);
            acc.w = fmaf(wgt, v.w, acc.w);
        }
        s_ax[ty][tx] = acc.x;
        s_ay[ty][tx] = acc.y;
        s_az[ty][tx] = acc.z;
        s_aw[ty][tx] = acc.w;
        __syncthreads();   // bar1: partials ready (also protects s_sig of prev tile)

        // warp w reduces pixel column w; lane reads channel-group `lane`.
        {
            float ax = s_ax[lane][w];
            float ay = s_ay[lane][w];
            float az = s_az[lane][w];
            float aw = s_aw[lane][w];
#pragma unroll
            for (int off = 16; off > 0; off >>= 1) {
                ax += __shfl_xor_sync(0xffffffffu, ax, off);
                ay += __shfl_xor_sync(0xffffffffu, ay, off);
                az += __shfl_xor_sync(0xffffffffu, az, off);
                aw += __shfl_xor_sync(0xffffffffu, aw, off);
            }
            if (lane == 0) {
                float4 sg;
                sg.x = 1.0f / (1.0f + __expf(-(ax + be)));
                sg.y = 1.0f / (1.0f + __expf(-(ay + be)));
                sg.z = 1.0f / (1.0f + __expf(-(az + be)));
                sg.w = 1.0f / (1.0f + __expf(-(aw + be)));
                s_sig[w] = sg;
            }
        }
        __syncthreads();   // bar2: sigmoids ready (also protects s_a reuse)

        const float4 sg = s_sig[tx];
#pragma unroll
        for (int i = 0; i < 8; i++) {
            float4 v = xv[i];
            float4 o;
            o.x = v.x * (atv[i] + sg.x);
            o.y = v.y * (atv[i] + sg.y);
            o.z = v.z * (atv[i] + sg.z);
            o.w = v.w * (atv[i] + sg.w);
            o4[(size_t)(c0 + i) * HW4 + pos4] = o;
        }
        // loop back: next tile's LDGs issue while these STGs drain.
    }
}

// ---------------------------------------------------------------------------
extern "C" void kernel_launch(void* const* d_in, const int* in_sizes, int n_in,
                              void* d_out, int out_size) {
    const float* x        = (const float*)d_in[0];
    const float* ch_cv1_w = (const float*)d_in[1];
    const float* ch_cv1_b = (const float*)d_in[2];
    // d_in[3], d_in[4]: ch_cv2_w/b — unused (softmax over size-1 axis == 1)
    const float* ch_cv3_w = (const float*)d_in[5];
    const float* ch_cv3_b = (const float*)d_in[6];
    const float* ln_g     = (const float*)d_in[7];
    const float* ln_b     = (const float*)d_in[8];
    const float* sp_cv1_w = (const float*)d_in[9];
    const float* sp_cv1_b = (const float*)d_in[10];
    const float* sp_cv2_w = (const float*)d_in[11];
    const float* sp_cv2_b = (const float*)d_in[12];
    float* out = (float*)d_out;

    k_sum<<<dim3(C_TOT, 4), 256>>>(x);
    k_small<<<1, 256>>>(ch_cv1_w, ch_cv1_b, ch_cv3_w, ch_cv3_b,
                        ln_g, ln_b, sp_cv1_w, sp_cv1_b, sp_cv2_w, sp_cv2_b);
    k_main<<<N_BLOCKS, dim3(16, 32)>>>(x, out);
}